// round 14
// baseline (speedup 1.0000x reference)
#include <cuda_runtime.h>
#include <math.h>
#include <stdint.h>

#define N_OBJ  100000
#define N_EVT  200000
#define N_EDGE 1000000
#define D      128
#define ESPLIT 100000   // event-range split for scatter/GEMM pipelining

// ---------------- scratch (device globals; no allocation) ----------------
__device__ float g_csum [(size_t)N_EVT * D];      // scatter-sum of objX rows
__device__ float g_cnt  [N_EVT];                  // edge counts per event
__device__ float g_h1   [(size_t)N_EVT * D];      // relu(...), tf32-rounded
__device__ float g_teff [(size_t)N_OBJ * D];      // scatter-add into objects
__device__ float g_gi   [(size_t)N_OBJ * 3 * D];  // x @ Wih^T + bih
__device__ float g_gh   [(size_t)N_OBJ * 3 * D];  // h @ Whh^T + bhh
__device__ float g_wrnd [163840];                 // tf32-rounded weights
__device__ float g_cvec [128];                    // W1b @ ba (fp32)

#define WR_WA   0        // unused slot (layout stability)
#define WR_W1   16384    // fused [W1a | Wc] rows of 256
#define WR_W2   49152
#define WR_WIH  65536
#define WR_WHH  114688

// ---------------- helpers ----------------
__device__ __forceinline__ uint32_t smem_u32(const void* p) {
    uint32_t a;
    asm("{ .reg .u64 t; cvta.to.shared.u64 t, %1; cvt.u32.u64 %0, t; }"
        : "=r"(a) : "l"(p));
    return a;
}

__device__ __forceinline__ uint32_t tf32r(float f) {
    uint32_t o;
    asm("cvt.rna.tf32.f32 %0, %1;" : "=r"(o) : "f"(f));
    return o;
}

__device__ __forceinline__ void cpasync16(uint32_t dst, const void* src, int sz) {
    asm volatile("cp.async.cg.shared.global [%0], [%1], 16, %2;"
                 :: "r"(dst), "l"(src), "r"(sz));
}

__device__ __forceinline__ void ldmx4(uint32_t* r, uint32_t addr) {
    asm volatile(
        "ldmatrix.sync.aligned.x4.m8n8.shared.b16 {%0,%1,%2,%3}, [%4];"
        : "=r"(r[0]), "=r"(r[1]), "=r"(r[2]), "=r"(r[3]) : "r"(addr));
}

__device__ __forceinline__ void red4(float* addr, float4 v) {
    asm volatile("red.global.add.v4.f32 [%0], {%1, %2, %3, %4};"
                 :: "l"(addr), "f"(v.x), "f"(v.y), "f"(v.z), "f"(v.w)
                 : "memory");
}

__device__ __forceinline__ float sigmoidf_(float x) {
    return 1.0f / (1.0f + expf(-x));
}

__device__ __forceinline__ void mma_tf32(float* c, const uint32_t* a,
                                         const uint32_t* b) {
    asm volatile(
        "mma.sync.aligned.m16n8k8.row.col.f32.tf32.tf32.f32 "
        "{%0,%1,%2,%3}, {%4,%5,%6,%7}, {%8,%9}, {%0,%1,%2,%3};"
        : "+f"(c[0]), "+f"(c[1]), "+f"(c[2]), "+f"(c[3])
        : "r"(a[0]), "r"(a[1]), "r"(a[2]), "r"(a[3]), "r"(b[0]), "r"(b[1]));
}

// ---------------- weight pre-rounding (skips W1 right half) -------------
__global__ void round_weights(const float* __restrict__ W1,
                              const float* __restrict__ W2,
                              const float* __restrict__ Wih,
                              const float* __restrict__ Whh) {
    int i = blockIdx.x * blockDim.x + threadIdx.x;
    if (i < WR_W1 || i >= 163840) return;
    float v;
    if (i < WR_W2) {
        int local = i - WR_W1;
        if ((local & 255) >= 128) return;   // Wc half, filled by wc_kernel
        v = W1[local];
    }
    else if (i < WR_WIH) v = W2 [i - WR_W2];
    else if (i < WR_WHH) v = Wih[i - WR_WIH];
    else                 v = Whh[i - WR_WHH];
    g_wrnd[i] = __uint_as_float(tf32r(v));
}

// ---------------- Wc = W1b @ Wa  (and cvec = W1b @ ba) ------------------
__global__ void wc_kernel(const float* __restrict__ W1,
                          const float* __restrict__ Wa,
                          const float* __restrict__ ba) {
    __shared__ float w1b[128];
    const int n = blockIdx.x;
    const int j = threadIdx.x;
    w1b[j] = W1[n * 256 + 128 + j];
    __syncthreads();
    float s = 0.f;
    #pragma unroll 4
    for (int k = 0; k < 128; k++)
        s = fmaf(w1b[k], Wa[k * 128 + j], s);
    g_wrnd[WR_W1 + n * 256 + 128 + j] = __uint_as_float(tf32r(s));
    if (j == 0) {
        float cs = 0.f;
        for (int k = 0; k < 128; k++) cs = fmaf(w1b[k], ba[k], cs);
        g_cvec[n] = cs;
    }
}

// ---------------- zeroing ------------------------------------------------
__global__ void zero_csum() {
    int i = blockIdx.x * blockDim.x + threadIdx.x;
    const int n1 = N_EVT * D / 4;
    const int n2 = N_EVT / 4;
    float4 z = make_float4(0.f, 0.f, 0.f, 0.f);
    if (i < n1) reinterpret_cast<float4*>(g_csum)[i] = z;
    if (i < n2) reinterpret_cast<float4*>(g_cnt)[i]  = z;
}

__global__ void zero_teff() {
    int i = blockIdx.x * blockDim.x + threadIdx.x;
    if (i < N_OBJ * D / 4)
        reinterpret_cast<float4*>(g_teff)[i] = make_float4(0.f, 0.f, 0.f, 0.f);
}

// =====================================================================
// tf32 mma.sync GEMM: cp.async 3-stage pipeline, BK=32, ldmatrix loads,
// SW128-style XOR swizzle on dense 128B SMEM rows. (R10 structure.)
// CTA tile 128x128, 256 threads = 8 warps (4m x 2n), warp 32x64.
// W row stride = K. CTX=1: A = [evX | csum*inv(cnt)] (row stride 128 each),
// K=256, cnt via cntp; epilogue adds beta*cvec.
// =====================================================================
#define BK     32
#define STAGES 3
#define STG_W  (128 * 32)
#define GEMM_SMEM (STAGES * STG_W * 2 * 4)    // 98304 bytes

template<int RELU, int CTX, int ACVT, int RNDOUT>
__global__ __launch_bounds__(256, 2)
void gemm_mma(const float* __restrict__ A, const float* __restrict__ A2,
              const float* __restrict__ cntp,
              const float* __restrict__ W,
              const float* __restrict__ bias, float* __restrict__ C,
              int M, int N, int K) {
    extern __shared__ uint32_t sm[];
    uint32_t* As = sm;
    uint32_t* Bs = sm + STAGES * STG_W;
    __shared__ float sinv[128];
    __shared__ float sbeta[128];

    const int tid = threadIdx.x;
    const int wid = tid >> 5;
    const int lane = tid & 31;
    const int gq = lane >> 2;
    const int tg = lane & 3;
    const int warp_m = wid >> 1;
    const int warp_n = wid & 1;
    const int bm = blockIdx.y * 128;
    const int bn = blockIdx.x * 128;

    const uint32_t aAs = smem_u32(As);
    const uint32_t aBs = smem_u32(Bs);

    const int r0 = tid >> 3;
    const int cb = (tid & 7) * 16;
    const int c4f = (tid & 7) * 4;

    uint32_t rowbA[2], swzA[2];
    #pragma unroll
    for (int mt = 0; mt < 2; mt++) {
        int row = warp_m * 32 + mt * 16 + (lane & 15);
        rowbA[mt] = (uint32_t)row * 128;
        swzA[mt] = (uint32_t)(row & 7) << 4;
    }
    const uint32_t hiA = (uint32_t)(lane >> 4) << 4;
    uint32_t rowbB[4], swzB[4];
    #pragma unroll
    for (int j = 0; j < 4; j++) {
        int n = warp_n * 64 + j * 16 + (lane & 7) + (((lane >> 4) & 1) << 3);
        rowbB[j] = (uint32_t)n * 128;
        swzB[j] = (uint32_t)(n & 7) << 4;
    }
    const uint32_t hiB = (lane & 8) ? 16u : 0u;

    float acc[2][8][4];
    #pragma unroll
    for (int i = 0; i < 2; i++)
        #pragma unroll
        for (int j = 0; j < 8; j++)
            #pragma unroll
            for (int q = 0; q < 4; q++) acc[i][j][q] = 0.f;

    const int CHUNKS = K >> 5;

    auto issue = [&](int c) {
        if (c < CHUNKS) {
            const int p = (c % STAGES);
            const int k0 = c * BK + c4f;
            const uint32_t dsw = (uint32_t)cb ^ ((uint32_t)(r0 & 7) << 4);
            #pragma unroll
            for (int h = 0; h < 4; h++) {
                int r = r0 + h * 32;
                const float* srcA;
                if (CTX) {
                    srcA = (k0 < 128)
                         ? &A [(size_t)(bm + r) * 128 + k0]
                         : &A2[(size_t)(bm + r) * 128 + (k0 - 128)];
                } else {
                    srcA = &A[(size_t)(bm + r) * K + k0];
                }
                int szA = (bm + r < M) ? 16 : 0;
                uint32_t doff = (uint32_t)(p * STG_W * 4) + (uint32_t)r * 128 + dsw;
                cpasync16(aAs + doff, srcA, szA);
                cpasync16(aBs + doff, &W[(size_t)(bn + r) * K + k0], 16);
            }
        }
        asm volatile("cp.async.commit_group;");
    };

    float invr[2][2];
    if (CTX) {
        if (tid < 128) {
            int r = bm + tid;
            float cv = (r < M) ? __ldg(&cntp[r]) : 1.0f;
            float iv = 1.0f / fmaxf(cv, 1.0f);
            sinv[tid] = iv;
            sbeta[tid] = cv * iv;
        }
    }

    issue(0); issue(1);
    if (CTX) __syncthreads();

    if (CTX) {
        #pragma unroll
        for (int mt = 0; mt < 2; mt++) {
            int row = warp_m * 32 + mt * 16 + gq;
            invr[mt][0] = sinv[row];
            invr[mt][1] = sinv[row + 8];
        }
    }

    for (int c = 0; c < CHUNKS; c++) {
        const int p = (c % STAGES);
        asm volatile("cp.async.wait_group 1;");
        __syncthreads();
        issue(c + 2);

        const bool scale = CTX && (c >= 4);
        const uint32_t stA = aAs + (uint32_t)(p * STG_W) * 4;
        const uint32_t stB = aBs + (uint32_t)(p * STG_W) * 4;
        #pragma unroll
        for (int ks = 0; ks < 4; ks++) {
            const uint32_t kc = (uint32_t)ks * 32;
            uint32_t af[2][4], bf[4][4];
            #pragma unroll
            for (int mt = 0; mt < 2; mt++)
                ldmx4(af[mt], stA + rowbA[mt] + ((kc + hiA) ^ swzA[mt]));
            #pragma unroll
            for (int j = 0; j < 4; j++)
                ldmx4(bf[j], stB + rowbB[j] + ((kc + hiB) ^ swzB[j]));

            if (ACVT) {
                #pragma unroll
                for (int mt = 0; mt < 2; mt++) {
                    float f0 = __uint_as_float(af[mt][0]);
                    float f1 = __uint_as_float(af[mt][1]);
                    float f2 = __uint_as_float(af[mt][2]);
                    float f3 = __uint_as_float(af[mt][3]);
                    if (scale) {
                        f0 *= invr[mt][0]; f1 *= invr[mt][1];
                        f2 *= invr[mt][0]; f3 *= invr[mt][1];
                    }
                    af[mt][0] = tf32r(f0); af[mt][1] = tf32r(f1);
                    af[mt][2] = tf32r(f2); af[mt][3] = tf32r(f3);
                }
            }
            #pragma unroll
            for (int mt = 0; mt < 2; mt++)
                #pragma unroll
                for (int nt = 0; nt < 8; nt++)
                    mma_tf32(acc[mt][nt], af[mt], &bf[nt >> 1][(nt & 1) * 2]);
        }
    }

    // epilogue
    #pragma unroll
    for (int mt = 0; mt < 2; mt++) {
        #pragma unroll
        for (int half = 0; half < 2; half++) {
            int mrow = warp_m * 32 + mt * 16 + gq + half * 8;
            int m = bm + mrow;
            if (m >= M) continue;
            float beta = CTX ? sbeta[mrow] : 0.f;
            #pragma unroll
            for (int nt = 0; nt < 8; nt++) {
                int n = bn + warp_n * 64 + nt * 8 + tg * 2;
                float2 bb = *reinterpret_cast<const float2*>(&bias[n]);
                float2 o;
                o.x = acc[mt][nt][half * 2 + 0] + bb.x;
                o.y = acc[mt][nt][half * 2 + 1] + bb.y;
                if (CTX) {
                    float2 cv = *reinterpret_cast<const float2*>(&g_cvec[n]);
                    o.x = fmaf(beta, cv.x, o.x);
                    o.y = fmaf(beta, cv.y, o.y);
                }
                if (RELU) { o.x = fmaxf(o.x, 0.f); o.y = fmaxf(o.y, 0.f); }
                if (RNDOUT) {
                    o.x = __uint_as_float(tf32r(o.x));
                    o.y = __uint_as_float(tf32r(o.y));
                }
                *reinterpret_cast<float2*>(&C[(size_t)m * N + n]) = o;
            }
        }
    }
}

// ------- edge scatter: objX[o] -> sum into events (ev in [lo,hi)) -------
__global__ void scatter_obj_to_evt(const int* __restrict__ obj_idx,
                                   const int* __restrict__ evt_idx,
                                   const float* __restrict__ objX,
                                   int lo, int hi) {
    int gid = blockIdx.x * blockDim.x + threadIdx.x;
    if (gid >= N_EDGE * 32) return;
    int e = gid >> 5;
    int c = gid & 31;
    int ev = __ldg(evt_idx + e);
    if (ev < lo || ev >= hi) return;
    int o = __ldg(obj_idx + e);
    float4 v = *reinterpret_cast<const float4*>(&objX[(size_t)o * D + c * 4]);
    red4(&g_csum[(size_t)ev * D + c * 4], v);
    if (c == 0) atomicAdd(&g_cnt[ev], 1.0f);
}

// ------- edge scatter: himp[ev] -> sum into objects (ev in [lo,hi)) -----
__global__ void scatter_evt_to_obj(const int* __restrict__ obj_idx,
                                   const int* __restrict__ evt_idx,
                                   const float* __restrict__ himp,
                                   int lo, int hi) {
    int gid = blockIdx.x * blockDim.x + threadIdx.x;
    if (gid >= N_EDGE * 32) return;
    int e = gid >> 5;
    int c = gid & 31;
    int ev = __ldg(evt_idx + e);
    if (ev < lo || ev >= hi) return;
    int o = __ldg(obj_idx + e);
    float4 v = *reinterpret_cast<const float4*>(&himp[(size_t)ev * D + c * 4]);
    red4(&g_teff[(size_t)o * D + c * 4], v);
}

// ---------------- GRU gate math -----------------------------------------
__global__ void gru_gates(const float* __restrict__ objX, float* __restrict__ out) {
    int gid = blockIdx.x * blockDim.x + threadIdx.x;
    if (gid >= N_OBJ * D) return;
    int r = gid >> 7;
    int d = gid & 127;
    size_t base = (size_t)r * 3 * D + d;
    float ir = g_gi[base], iz = g_gi[base + D], in_ = g_gi[base + 2 * D];
    float hr = g_gh[base], hz = g_gh[base + D], hn  = g_gh[base + 2 * D];
    float h = objX[(size_t)r * D + d];
    float rg = sigmoidf_(ir + hr);
    float z  = sigmoidf_(iz + hz);
    float n  = tanhf(in_ + rg * hn);
    out[(size_t)r * D + d] = (1.0f - z) * n + z * h;
}

// ---------------- launch ------------------------------------------------
extern "C" void kernel_launch(void* const* d_in, const int* in_sizes, int n_in,
                              void* d_out, int out_size) {
    const float* event_X  = (const float*)d_in[0];
    const float* object_X = (const float*)d_in[1];
    const int*   evt_idx  = (const int*)d_in[2];
    const int*   obj_idx  = (const int*)d_in[3];
    const float* Wa  = (const float*)d_in[4];
    const float* ba  = (const float*)d_in[5];
    const float* W1  = (const float*)d_in[6];
    const float* b1  = (const float*)d_in[7];
    const float* W2  = (const float*)d_in[8];
    const float* b2  = (const float*)d_in[9];
    const float* Wih = (const float*)d_in[10];
    const float* Whh = (const float*)d_in[11];
    const float* bih = (const float*)d_in[12];
    const float* bhh = (const float*)d_in[13];

    float* out = (float*)d_out;
    float* out_newobj = out;                       // [N_OBJ, 128]
    float* out_himp   = out + (size_t)N_OBJ * D;   // [N_EVT, 128]

    float* csum  = nullptr; cudaGetSymbolAddress((void**)&csum,  g_csum);
    float* cnt   = nullptr; cudaGetSymbolAddress((void**)&cnt,   g_cnt);
    float* h1    = nullptr; cudaGetSymbolAddress((void**)&h1,    g_h1);
    float* teff  = nullptr; cudaGetSymbolAddress((void**)&teff,  g_teff);
    float* gi    = nullptr; cudaGetSymbolAddress((void**)&gi,    g_gi);
    float* gh    = nullptr; cudaGetSymbolAddress((void**)&gh,    g_gh);
    float* wr    = nullptr; cudaGetSymbolAddress((void**)&wr,    g_wrnd);

    static cudaStream_t sW = nullptr, sP = nullptr;
    static cudaEvent_t eFork, eW, eGh, eZT, eS1A, eS1B, eHA, eS2A;
    if (!sW) {
        cudaStreamCreateWithFlags(&sW, cudaStreamNonBlocking);
        cudaStreamCreateWithFlags(&sP, cudaStreamNonBlocking);
        cudaEventCreateWithFlags(&eFork, cudaEventDisableTiming);
        cudaEventCreateWithFlags(&eW,   cudaEventDisableTiming);
        cudaEventCreateWithFlags(&eGh,  cudaEventDisableTiming);
        cudaEventCreateWithFlags(&eZT,  cudaEventDisableTiming);
        cudaEventCreateWithFlags(&eS1A, cudaEventDisableTiming);
        cudaEventCreateWithFlags(&eS1B, cudaEventDisableTiming);
        cudaEventCreateWithFlags(&eHA,  cudaEventDisableTiming);
        cudaEventCreateWithFlags(&eS2A, cudaEventDisableTiming);
        cudaFuncSetAttribute(gemm_mma<0, 0, 1, 0>,
            cudaFuncAttributeMaxDynamicSharedMemorySize, GEMM_SMEM);
        cudaFuncSetAttribute(gemm_mma<1, 1, 1, 1>,
            cudaFuncAttributeMaxDynamicSharedMemorySize, GEMM_SMEM);
        cudaFuncSetAttribute(gemm_mma<0, 0, 0, 0>,
            cudaFuncAttributeMaxDynamicSharedMemorySize, GEMM_SMEM);
    }

    const int SGRID = (N_EDGE * 32 + 255) / 256;

    // fork side stream: weight prep, gh GEMM, teff zero
    cudaEventRecord(eFork, 0);
    cudaStreamWaitEvent(sW, eFork, 0);
    round_weights<<<(163840 + 255) / 256, 256, 0, sW>>>(W1, W2, Wih, Whh);
    wc_kernel<<<128, 128, 0, sW>>>(W1, Wa, ba);
    cudaEventRecord(eW, sW);
    gemm_mma<0, 0, 1, 0><<<dim3(3, (N_OBJ + 127) / 128), 256, GEMM_SMEM, sW>>>(
        object_X, nullptr, nullptr, wr + WR_WHH, bhh, gh, N_OBJ, 3 * D, D);
    cudaEventRecord(eGh, sW);
    zero_teff<<<(N_OBJ * D / 4 + 255) / 256, 256, 0, sW>>>();
    cudaEventRecord(eZT, sW);

    // main: zero csum+cnt, scatter1 pass A (ev < ESPLIT)
    zero_csum<<<(N_EVT * D / 4 + 255) / 256, 256>>>();
    scatter_obj_to_evt<<<SGRID, 256>>>(obj_idx, evt_idx, object_X, 0, ESPLIT);
    cudaEventRecord(eS1A, 0);

    // pipeline stream: scatter1 pass B concurrent with ctxA
    cudaStreamWaitEvent(sP, eS1A, 0);
    scatter_obj_to_evt<<<SGRID, 256, 0, sP>>>(obj_idx, evt_idx, object_X,
                                              ESPLIT, N_EVT);
    cudaEventRecord(eS1B, sP);

    // main: ctxA = rows [0, ESPLIT)
    cudaStreamWaitEvent(0, eW, 0);
    gemm_mma<1, 1, 1, 1><<<dim3(1, (ESPLIT + 127) / 128), 256, GEMM_SMEM>>>(
        event_X, csum, cnt, wr + WR_W1, b1, h1, ESPLIT, D, 2 * D);
    // ctxB = rows [ESPLIT, N_EVT)
    cudaStreamWaitEvent(0, eS1B, 0);
    gemm_mma<1, 1, 1, 1><<<dim3(1, (N_EVT - ESPLIT + 127) / 128), 256, GEMM_SMEM>>>(
        event_X + (size_t)ESPLIT * D, csum + (size_t)ESPLIT * D, cnt + ESPLIT,
        wr + WR_W1, b1, h1 + (size_t)ESPLIT * D, N_EVT - ESPLIT, D, 2 * D);

    // himpA = rows [0, ESPLIT)
    gemm_mma<0, 0, 0, 0><<<dim3(1, (ESPLIT + 127) / 128), 256, GEMM_SMEM>>>(
        h1, nullptr, nullptr, wr + WR_W2, b2, out_himp, ESPLIT, D, D);
    cudaEventRecord(eHA, 0);
    // himpB = rows [ESPLIT, N_EVT)
    gemm_mma<0, 0, 0, 0><<<dim3(1, (N_EVT - ESPLIT + 127) / 128), 256, GEMM_SMEM>>>(
        h1 + (size_t)ESPLIT * D, nullptr, nullptr, wr + WR_W2, b2,
        out_himp + (size_t)ESPLIT * D, N_EVT - ESPLIT, D, D);

    // pipeline stream: scatter2 pass A (ev < ESPLIT) concurrent with himpB
    cudaStreamWaitEvent(sP, eHA, 0);
    cudaStreamWaitEvent(sP, eZT, 0);
    scatter_evt_to_obj<<<SGRID, 256, 0, sP>>>(obj_idx, evt_idx, out_himp,
                                              0, ESPLIT);
    cudaEventRecord(eS2A, sP);

    // main: scatter2 pass B (after himpB; teff zeroed via eZT)
    cudaStreamWaitEvent(0, eZT, 0);
    scatter_evt_to_obj<<<SGRID, 256>>>(obj_idx, evt_idx, out_himp,
                                       ESPLIT, N_EVT);

    // gi = total_effect @ Wih^T + bih (join scatter2A)
    cudaStreamWaitEvent(0, eS2A, 0);
    gemm_mma<0, 0, 1, 0><<<dim3(3, (N_OBJ + 127) / 128), 256, GEMM_SMEM>>>(
        teff, nullptr, nullptr, wr + WR_WIH, bih, gi, N_OBJ, 3 * D, D);

    // join gh, then GRU gates -> new_object_X
    cudaStreamWaitEvent(0, eGh, 0);
    gru_gates<<<(N_OBJ * D + 255) / 256, 256>>>(object_X, out_newobj);
}

// round 15
// speedup vs baseline: 1.2478x; 1.2478x over previous
#include <cuda_runtime.h>
#include <math.h>
#include <stdint.h>

#define N_OBJ  100000
#define N_EVT  200000
#define N_EDGE 1000000
#define D      128

// ---------------- scratch (device globals; no allocation) ----------------
__device__ float g_csum [(size_t)N_EVT * D];      // scatter-sum of objX rows
__device__ float g_cnt  [N_EVT];                  // edge counts per event
__device__ float g_h1   [(size_t)N_EVT * D];      // relu(...), tf32-rounded
__device__ float g_teff [(size_t)N_OBJ * D];      // scatter-add into objects
__device__ float g_gi   [(size_t)N_OBJ * 3 * D];  // x @ Wih^T + bih
__device__ float g_gh   [(size_t)N_OBJ * 3 * D];  // h @ Whh^T + bhh
__device__ float g_wrnd [163840];                 // tf32-rounded weights
__device__ float g_cvec [128];                    // W1b @ ba (fp32)

#define WR_WA   0        // unused slot (layout stability)
#define WR_W1   16384    // fused [W1a | Wc] rows of 256
#define WR_W2   49152
#define WR_WIH  65536
#define WR_WHH  114688

// ---------------- helpers ----------------
__device__ __forceinline__ uint32_t smem_u32(const void* p) {
    uint32_t a;
    asm("{ .reg .u64 t; cvta.to.shared.u64 t, %1; cvt.u32.u64 %0, t; }"
        : "=r"(a) : "l"(p));
    return a;
}

__device__ __forceinline__ uint32_t tf32r(float f) {
    uint32_t o;
    asm("cvt.rna.tf32.f32 %0, %1;" : "=r"(o) : "f"(f));
    return o;
}

__device__ __forceinline__ void cpasync16(uint32_t dst, const void* src, int sz) {
    asm volatile("cp.async.cg.shared.global [%0], [%1], 16, %2;"
                 :: "r"(dst), "l"(src), "r"(sz));
}

__device__ __forceinline__ void ldmx4(uint32_t* r, uint32_t addr) {
    asm volatile(
        "ldmatrix.sync.aligned.x4.m8n8.shared.b16 {%0,%1,%2,%3}, [%4];"
        : "=r"(r[0]), "=r"(r[1]), "=r"(r[2]), "=r"(r[3]) : "r"(addr));
}

__device__ __forceinline__ void red4(float* addr, float4 v) {
    asm volatile("red.global.add.v4.f32 [%0], {%1, %2, %3, %4};"
                 :: "l"(addr), "f"(v.x), "f"(v.y), "f"(v.z), "f"(v.w)
                 : "memory");
}

__device__ __forceinline__ float sigmoidf_(float x) {
    return 1.0f / (1.0f + expf(-x));
}

__device__ __forceinline__ void mma_tf32(float* c, const uint32_t* a,
                                         const uint32_t* b) {
    asm volatile(
        "mma.sync.aligned.m16n8k8.row.col.f32.tf32.tf32.f32 "
        "{%0,%1,%2,%3}, {%4,%5,%6,%7}, {%8,%9}, {%0,%1,%2,%3};"
        : "+f"(c[0]), "+f"(c[1]), "+f"(c[2]), "+f"(c[3])
        : "r"(a[0]), "r"(a[1]), "r"(a[2]), "r"(a[3]), "r"(b[0]), "r"(b[1]));
}

// ---------------- weight pre-rounding (skips W1 right half) -------------
__global__ void round_weights(const float* __restrict__ W1,
                              const float* __restrict__ W2,
                              const float* __restrict__ Wih,
                              const float* __restrict__ Whh) {
    int i = blockIdx.x * blockDim.x + threadIdx.x;
    if (i < WR_W1 || i >= 163840) return;
    float v;
    if (i < WR_W2) {
        int local = i - WR_W1;
        if ((local & 255) >= 128) return;   // Wc half, filled by wc_kernel
        v = W1[local];
    }
    else if (i < WR_WIH) v = W2 [i - WR_W2];
    else if (i < WR_WHH) v = Wih[i - WR_WIH];
    else                 v = Whh[i - WR_WHH];
    g_wrnd[i] = __uint_as_float(tf32r(v));
}

// ---------------- Wc = W1b @ Wa  (and cvec = W1b @ ba) ------------------
__global__ void wc_kernel(const float* __restrict__ W1,
                          const float* __restrict__ Wa,
                          const float* __restrict__ ba) {
    __shared__ float w1b[128];
    const int n = blockIdx.x;
    const int j = threadIdx.x;
    w1b[j] = W1[n * 256 + 128 + j];
    __syncthreads();
    float s = 0.f;
    #pragma unroll 4
    for (int k = 0; k < 128; k++)
        s = fmaf(w1b[k], Wa[k * 128 + j], s);
    g_wrnd[WR_W1 + n * 256 + 128 + j] = __uint_as_float(tf32r(s));
    if (j == 0) {
        float cs = 0.f;
        for (int k = 0; k < 128; k++) cs = fmaf(w1b[k], ba[k], cs);
        g_cvec[n] = cs;
    }
}

// ---------------- zeroing ------------------------------------------------
__global__ void zero_csum() {
    int i = blockIdx.x * blockDim.x + threadIdx.x;
    const int n1 = N_EVT * D / 4;
    const int n2 = N_EVT / 4;
    float4 z = make_float4(0.f, 0.f, 0.f, 0.f);
    if (i < n1) reinterpret_cast<float4*>(g_csum)[i] = z;
    if (i < n2) reinterpret_cast<float4*>(g_cnt)[i]  = z;
}

__global__ void zero_teff() {
    int i = blockIdx.x * blockDim.x + threadIdx.x;
    if (i < N_OBJ * D / 4)
        reinterpret_cast<float4*>(g_teff)[i] = make_float4(0.f, 0.f, 0.f, 0.f);
}

// =====================================================================
// tf32 mma.sync GEMM: cp.async 3-stage pipeline, BK=32, ldmatrix loads,
// SW128-style XOR swizzle on dense 128B SMEM rows.
// CTA tile 256x128, 512 threads = 16 warps (8m x 2n), warp 32x64.
// 1 CTA/SM, 16 warps/SM; B tile traffic halved vs 128x128.
// W row stride = K. CTX=1: A = [evX | csum*inv(cnt)] (row stride 128 each),
// K=256; epilogue adds beta*cvec. g_cnt/g_cvec read directly.
// =====================================================================
#define BK      32
#define STAGES  3
#define STG_A_W (256 * 32)   // words per A stage (32KB)
#define STG_B_W (128 * 32)   // words per B stage (16KB)
#define GEMM_SMEM (STAGES * (STG_A_W + STG_B_W) * 4)   // 147456 bytes

template<int RELU, int CTX, int ACVT, int RNDOUT>
__global__ __launch_bounds__(512, 1)
void gemm_mma(const float* __restrict__ A, const float* __restrict__ A2,
              const float* __restrict__ W,
              const float* __restrict__ bias, float* __restrict__ C,
              int M, int N, int K) {
    extern __shared__ uint32_t sm[];
    uint32_t* As = sm;
    uint32_t* Bs = sm + STAGES * STG_A_W;
    __shared__ float sinv[256];
    __shared__ float sbeta[256];

    const int tid = threadIdx.x;
    const int wid = tid >> 5;
    const int lane = tid & 31;
    const int gq = lane >> 2;
    const int tg = lane & 3;
    const int warp_m = wid >> 1;   // 0..7 -> 32 rows each
    const int warp_n = wid & 1;    // 0..1 -> 64 cols each
    const int bm = blockIdx.y * 256;
    const int bn = blockIdx.x * 128;

    const uint32_t aAs = smem_u32(As);
    const uint32_t aBs = smem_u32(Bs);

    const int r0 = tid >> 3;              // 0..63
    const int cb = (tid & 7) * 16;
    const int c4f = (tid & 7) * 4;

    uint32_t rowbA[2], swzA[2];
    #pragma unroll
    for (int mt = 0; mt < 2; mt++) {
        int row = warp_m * 32 + mt * 16 + (lane & 15);
        rowbA[mt] = (uint32_t)row * 128;
        swzA[mt] = (uint32_t)(row & 7) << 4;
    }
    const uint32_t hiA = (uint32_t)(lane >> 4) << 4;
    uint32_t rowbB[4], swzB[4];
    #pragma unroll
    for (int j = 0; j < 4; j++) {
        int n = warp_n * 64 + j * 16 + (lane & 7) + (((lane >> 4) & 1) << 3);
        rowbB[j] = (uint32_t)n * 128;
        swzB[j] = (uint32_t)(n & 7) << 4;
    }
    const uint32_t hiB = (lane & 8) ? 16u : 0u;

    float acc[2][8][4];
    #pragma unroll
    for (int i = 0; i < 2; i++)
        #pragma unroll
        for (int j = 0; j < 8; j++)
            #pragma unroll
            for (int q = 0; q < 4; q++) acc[i][j][q] = 0.f;

    const int CHUNKS = K >> 5;

    auto issue = [&](int c) {
        if (c < CHUNKS) {
            const int p = (c % STAGES);
            const int k0 = c * BK + c4f;
            const uint32_t dsw = (uint32_t)cb ^ ((uint32_t)(r0 & 7) << 4);
            // A: 4 rows per thread (256 rows total)
            #pragma unroll
            for (int h = 0; h < 4; h++) {
                int r = r0 + h * 64;
                const float* srcA;
                if (CTX) {
                    srcA = (k0 < 128)
                         ? &A [(size_t)(bm + r) * 128 + k0]
                         : &A2[(size_t)(bm + r) * 128 + (k0 - 128)];
                } else {
                    srcA = &A[(size_t)(bm + r) * K + k0];
                }
                int szA = (bm + r < M) ? 16 : 0;
                uint32_t doff = (uint32_t)(p * STG_A_W * 4) + (uint32_t)r * 128 + dsw;
                cpasync16(aAs + doff, srcA, szA);
            }
            // B: 2 rows per thread (128 rows total)
            #pragma unroll
            for (int h = 0; h < 2; h++) {
                int r = r0 + h * 64;
                uint32_t doff = (uint32_t)(p * STG_B_W * 4) + (uint32_t)r * 128 + dsw;
                cpasync16(aBs + doff, &W[(size_t)(bn + r) * K + k0], 16);
            }
        }
        asm volatile("cp.async.commit_group;");
    };

    float invr[2][2];
    if (CTX) {
        if (tid < 256) {
            int r = bm + tid;
            float cv = (r < M) ? __ldg(&g_cnt[r]) : 1.0f;
            float iv = 1.0f / fmaxf(cv, 1.0f);
            sinv[tid] = iv;
            sbeta[tid] = cv * iv;
        }
    }

    issue(0); issue(1);
    if (CTX) __syncthreads();

    if (CTX) {
        #pragma unroll
        for (int mt = 0; mt < 2; mt++) {
            int row = warp_m * 32 + mt * 16 + gq;
            invr[mt][0] = sinv[row];
            invr[mt][1] = sinv[row + 8];
        }
    }

    for (int c = 0; c < CHUNKS; c++) {
        const int p = (c % STAGES);
        asm volatile("cp.async.wait_group 1;");
        __syncthreads();
        issue(c + 2);

        const bool scale = CTX && (c >= 4);
        const uint32_t stA = aAs + (uint32_t)(p * STG_A_W) * 4;
        const uint32_t stB = aBs + (uint32_t)(p * STG_B_W) * 4;
        #pragma unroll
        for (int ks = 0; ks < 4; ks++) {
            const uint32_t kc = (uint32_t)ks * 32;
            uint32_t af[2][4], bf[4][4];
            #pragma unroll
            for (int mt = 0; mt < 2; mt++)
                ldmx4(af[mt], stA + rowbA[mt] + ((kc + hiA) ^ swzA[mt]));
            #pragma unroll
            for (int j = 0; j < 4; j++)
                ldmx4(bf[j], stB + rowbB[j] + ((kc + hiB) ^ swzB[j]));

            if (ACVT) {
                #pragma unroll
                for (int mt = 0; mt < 2; mt++) {
                    float f0 = __uint_as_float(af[mt][0]);
                    float f1 = __uint_as_float(af[mt][1]);
                    float f2 = __uint_as_float(af[mt][2]);
                    float f3 = __uint_as_float(af[mt][3]);
                    if (scale) {
                        f0 *= invr[mt][0]; f1 *= invr[mt][1];
                        f2 *= invr[mt][0]; f3 *= invr[mt][1];
                    }
                    af[mt][0] = tf32r(f0); af[mt][1] = tf32r(f1);
                    af[mt][2] = tf32r(f2); af[mt][3] = tf32r(f3);
                }
            }
            #pragma unroll
            for (int mt = 0; mt < 2; mt++)
                #pragma unroll
                for (int nt = 0; nt < 8; nt++)
                    mma_tf32(acc[mt][nt], af[mt], &bf[nt >> 1][(nt & 1) * 2]);
        }
    }

    // epilogue
    #pragma unroll
    for (int mt = 0; mt < 2; mt++) {
        #pragma unroll
        for (int half = 0; half < 2; half++) {
            int mrow = warp_m * 32 + mt * 16 + gq + half * 8;
            int m = bm + mrow;
            if (m >= M) continue;
            float beta = CTX ? sbeta[mrow] : 0.f;
            #pragma unroll
            for (int nt = 0; nt < 8; nt++) {
                int n = bn + warp_n * 64 + nt * 8 + tg * 2;
                float2 bb = *reinterpret_cast<const float2*>(&bias[n]);
                float2 o;
                o.x = acc[mt][nt][half * 2 + 0] + bb.x;
                o.y = acc[mt][nt][half * 2 + 1] + bb.y;
                if (CTX) {
                    float2 cv = *reinterpret_cast<const float2*>(&g_cvec[n]);
                    o.x = fmaf(beta, cv.x, o.x);
                    o.y = fmaf(beta, cv.y, o.y);
                }
                if (RELU) { o.x = fmaxf(o.x, 0.f); o.y = fmaxf(o.y, 0.f); }
                if (RNDOUT) {
                    o.x = __uint_as_float(tf32r(o.x));
                    o.y = __uint_as_float(tf32r(o.y));
                }
                *reinterpret_cast<float2*>(&C[(size_t)m * N + n]) = o;
            }
        }
    }
}

// ---------------- edge scatter: objX[o] -> sum into events + counts -----
__global__ void scatter_obj_to_evt(const int* __restrict__ obj_idx,
                                   const int* __restrict__ evt_idx,
                                   const float* __restrict__ objX) {
    int gid = blockIdx.x * blockDim.x + threadIdx.x;
    if (gid >= N_EDGE * 32) return;
    int e = gid >> 5;
    int c = gid & 31;
    int o  = __ldg(obj_idx + e);
    int ev = __ldg(evt_idx + e);
    float4 v = *reinterpret_cast<const float4*>(&objX[(size_t)o * D + c * 4]);
    red4(&g_csum[(size_t)ev * D + c * 4], v);
    if (c == 0) atomicAdd(&g_cnt[ev], 1.0f);
}

// ---------------- edge scatter: h_impulse[evt] -> sum into objects ------
__global__ void scatter_evt_to_obj(const int* __restrict__ obj_idx,
                                   const int* __restrict__ evt_idx,
                                   const float* __restrict__ himp) {
    int gid = blockIdx.x * blockDim.x + threadIdx.x;
    if (gid >= N_EDGE * 32) return;
    int e = gid >> 5;
    int c = gid & 31;
    int o  = __ldg(obj_idx + e);
    int ev = __ldg(evt_idx + e);
    float4 v = *reinterpret_cast<const float4*>(&himp[(size_t)ev * D + c * 4]);
    red4(&g_teff[(size_t)o * D + c * 4], v);
}

// ---------------- GRU gate math -----------------------------------------
__global__ void gru_gates(const float* __restrict__ objX, float* __restrict__ out) {
    int gid = blockIdx.x * blockDim.x + threadIdx.x;
    if (gid >= N_OBJ * D) return;
    int r = gid >> 7;
    int d = gid & 127;
    size_t base = (size_t)r * 3 * D + d;
    float ir = g_gi[base], iz = g_gi[base + D], in_ = g_gi[base + 2 * D];
    float hr = g_gh[base], hz = g_gh[base + D], hn  = g_gh[base + 2 * D];
    float h = objX[(size_t)r * D + d];
    float rg = sigmoidf_(ir + hr);
    float z  = sigmoidf_(iz + hz);
    float n  = tanhf(in_ + rg * hn);
    out[(size_t)r * D + d] = (1.0f - z) * n + z * h;
}

// ---------------- launch ------------------------------------------------
extern "C" void kernel_launch(void* const* d_in, const int* in_sizes, int n_in,
                              void* d_out, int out_size) {
    const float* event_X  = (const float*)d_in[0];
    const float* object_X = (const float*)d_in[1];
    const int*   evt_idx  = (const int*)d_in[2];
    const int*   obj_idx  = (const int*)d_in[3];
    const float* Wa  = (const float*)d_in[4];
    const float* ba  = (const float*)d_in[5];
    const float* W1  = (const float*)d_in[6];
    const float* b1  = (const float*)d_in[7];
    const float* W2  = (const float*)d_in[8];
    const float* b2  = (const float*)d_in[9];
    const float* Wih = (const float*)d_in[10];
    const float* Whh = (const float*)d_in[11];
    const float* bih = (const float*)d_in[12];
    const float* bhh = (const float*)d_in[13];

    float* out = (float*)d_out;
    float* out_newobj = out;                       // [N_OBJ, 128]
    float* out_himp   = out + (size_t)N_OBJ * D;   // [N_EVT, 128]

    float* csum  = nullptr; cudaGetSymbolAddress((void**)&csum,  g_csum);
    float* h1    = nullptr; cudaGetSymbolAddress((void**)&h1,    g_h1);
    float* teff  = nullptr; cudaGetSymbolAddress((void**)&teff,  g_teff);
    float* gi    = nullptr; cudaGetSymbolAddress((void**)&gi,    g_gi);
    float* gh    = nullptr; cudaGetSymbolAddress((void**)&gh,    g_gh);
    float* wr    = nullptr; cudaGetSymbolAddress((void**)&wr,    g_wrnd);

    static cudaStream_t sW = nullptr;
    static cudaEvent_t eFork, eW, eGh, eZT;
    if (!sW) {
        cudaStreamCreateWithFlags(&sW, cudaStreamNonBlocking);
        cudaEventCreateWithFlags(&eFork, cudaEventDisableTiming);
        cudaEventCreateWithFlags(&eW,   cudaEventDisableTiming);
        cudaEventCreateWithFlags(&eGh,  cudaEventDisableTiming);
        cudaEventCreateWithFlags(&eZT,  cudaEventDisableTiming);
        cudaFuncSetAttribute(gemm_mma<0, 0, 1, 0>,
            cudaFuncAttributeMaxDynamicSharedMemorySize, GEMM_SMEM);
        cudaFuncSetAttribute(gemm_mma<1, 1, 1, 1>,
            cudaFuncAttributeMaxDynamicSharedMemorySize, GEMM_SMEM);
        cudaFuncSetAttribute(gemm_mma<0, 0, 0, 0>,
            cudaFuncAttributeMaxDynamicSharedMemorySize, GEMM_SMEM);
    }

    // fork side stream: weight prep, gh GEMM, teff zero
    cudaEventRecord(eFork, 0);
    cudaStreamWaitEvent(sW, eFork, 0);
    round_weights<<<(163840 + 255) / 256, 256, 0, sW>>>(W1, W2, Wih, Whh);
    wc_kernel<<<128, 128, 0, sW>>>(W1, Wa, ba);
    cudaEventRecord(eW, sW);
    gemm_mma<0, 0, 1, 0><<<dim3(3, (N_OBJ + 255) / 256), 512, GEMM_SMEM, sW>>>(
        object_X, nullptr, wr + WR_WHH, bhh, gh, N_OBJ, 3 * D, D);
    cudaEventRecord(eGh, sW);
    zero_teff<<<(N_OBJ * D / 4 + 255) / 256, 256, 0, sW>>>();
    cudaEventRecord(eZT, sW);

    // main: zero csum+cnt -> scatter objX into events
    zero_csum<<<(N_EVT * D / 4 + 255) / 256, 256>>>();
    scatter_obj_to_evt<<<(N_EDGE * 32 + 255) / 256, 256>>>(obj_idx, evt_idx,
                                                           object_X);

    // h1 = relu(evX@W1a^T + mean_obj@Wc^T + b1 + beta*cvec)
    cudaStreamWaitEvent(0, eW, 0);
    gemm_mma<1, 1, 1, 1><<<dim3(1, (N_EVT + 255) / 256), 512, GEMM_SMEM>>>(
        event_X, csum, wr + WR_W1, b1, h1, N_EVT, D, 2 * D);

    // h_impulse = h1 @ W2^T + b2 -> output
    gemm_mma<0, 0, 0, 0><<<dim3(1, (N_EVT + 255) / 256), 512, GEMM_SMEM>>>(
        h1, nullptr, wr + WR_W2, b2, out_himp, N_EVT, D, D);

    // scatter-add impulses into objects (teff zeroed on side stream)
    cudaStreamWaitEvent(0, eZT, 0);
    scatter_evt_to_obj<<<(N_EDGE * 32 + 255) / 256, 256>>>(obj_idx, evt_idx,
                                                           out_himp);

    // gi = total_effect @ Wih^T + bih
    gemm_mma<0, 0, 1, 0><<<dim3(3, (N_OBJ + 255) / 256), 512, GEMM_SMEM>>>(
        teff, nullptr, wr + WR_WIH, bih, gi, N_OBJ, 3 * D, D);

    // join gh, then GRU gates -> new_object_X
    cudaStreamWaitEvent(0, eGh, 0);
    gru_gates<<<(N_OBJ * D + 255) / 256, 256>>>(object_X, out_newobj);
}

// round 16
// speedup vs baseline: 1.3432x; 1.0765x over previous
#include <cuda_runtime.h>
#include <math.h>
#include <stdint.h>

#define N_OBJ  100000
#define N_EVT  200000
#define N_EDGE 1000000
#define D      128

// ---------------- scratch (device globals; no allocation) ----------------
__device__ float g_csum [(size_t)N_EVT * D];      // scatter-sum of objX rows
__device__ float g_cnt  [N_EVT];                  // edge counts per event
__device__ float g_h1   [(size_t)N_EVT * D];      // relu(...), tf32-rounded
__device__ float g_teff [(size_t)N_OBJ * D];      // scatter-add into objects
__device__ float g_gi   [(size_t)N_OBJ * 3 * D];  // x @ Wih^T + bih
__device__ float g_gh   [(size_t)N_OBJ * 3 * D];  // h @ Whh^T + bhh
__device__ float g_wrnd [163840];                 // tf32-rounded weights
__device__ float g_cvec [128];                    // W1b @ ba (fp32)

#define WR_WA   0        // unused slot (layout stability)
#define WR_W1   16384    // fused [W1a | Wc] rows of 256
#define WR_W2   49152
#define WR_WIH  65536
#define WR_WHH  114688

// ---------------- helpers ----------------
__device__ __forceinline__ uint32_t smem_u32(const void* p) {
    uint32_t a;
    asm("{ .reg .u64 t; cvta.to.shared.u64 t, %1; cvt.u32.u64 %0, t; }"
        : "=r"(a) : "l"(p));
    return a;
}

__device__ __forceinline__ uint32_t tf32r(float f) {
    uint32_t o;
    asm("cvt.rna.tf32.f32 %0, %1;" : "=r"(o) : "f"(f));
    return o;
}

__device__ __forceinline__ void cpasync16(uint32_t dst, const void* src, int sz) {
    asm volatile("cp.async.cg.shared.global [%0], [%1], 16, %2;"
                 :: "r"(dst), "l"(src), "r"(sz));
}

__device__ __forceinline__ void ldmx4(uint32_t* r, uint32_t addr) {
    asm volatile(
        "ldmatrix.sync.aligned.x4.m8n8.shared.b16 {%0,%1,%2,%3}, [%4];"
        : "=r"(r[0]), "=r"(r[1]), "=r"(r[2]), "=r"(r[3]) : "r"(addr));
}

__device__ __forceinline__ void red4(float* addr, float4 v) {
    asm volatile("red.global.add.v4.f32 [%0], {%1, %2, %3, %4};"
                 :: "l"(addr), "f"(v.x), "f"(v.y), "f"(v.z), "f"(v.w)
                 : "memory");
}

__device__ __forceinline__ float sigmoidf_(float x) {
    return 1.0f / (1.0f + expf(-x));
}

__device__ __forceinline__ void mma_tf32(float* c, const uint32_t* a,
                                         const uint32_t* b) {
    asm volatile(
        "mma.sync.aligned.m16n8k8.row.col.f32.tf32.tf32.f32 "
        "{%0,%1,%2,%3}, {%4,%5,%6,%7}, {%8,%9}, {%0,%1,%2,%3};"
        : "+f"(c[0]), "+f"(c[1]), "+f"(c[2]), "+f"(c[3])
        : "r"(a[0]), "r"(a[1]), "r"(a[2]), "r"(a[3]), "r"(b[0]), "r"(b[1]));
}

// ---------------- weight pre-rounding (skips W1 right half) -------------
__global__ void round_weights(const float* __restrict__ W1,
                              const float* __restrict__ W2,
                              const float* __restrict__ Wih,
                              const float* __restrict__ Whh) {
    int i = blockIdx.x * blockDim.x + threadIdx.x;
    if (i < WR_W1 || i >= 163840) return;
    float v;
    if (i < WR_W2) {
        int local = i - WR_W1;
        if ((local & 255) >= 128) return;   // Wc half, filled by wc_kernel
        v = W1[local];
    }
    else if (i < WR_WIH) v = W2 [i - WR_W2];
    else if (i < WR_WHH) v = Wih[i - WR_WIH];
    else                 v = Whh[i - WR_WHH];
    g_wrnd[i] = __uint_as_float(tf32r(v));
}

// ---------------- Wc = W1b @ Wa  (and cvec = W1b @ ba) ------------------
__global__ void wc_kernel(const float* __restrict__ W1,
                          const float* __restrict__ Wa,
                          const float* __restrict__ ba) {
    __shared__ float w1b[128];
    const int n = blockIdx.x;
    const int j = threadIdx.x;
    w1b[j] = W1[n * 256 + 128 + j];
    __syncthreads();
    float s = 0.f;
    #pragma unroll 4
    for (int k = 0; k < 128; k++)
        s = fmaf(w1b[k], Wa[k * 128 + j], s);
    g_wrnd[WR_W1 + n * 256 + 128 + j] = __uint_as_float(tf32r(s));
    if (j == 0) {
        float cs = 0.f;
        for (int k = 0; k < 128; k++) cs = fmaf(w1b[k], ba[k], cs);
        g_cvec[n] = cs;
    }
}

// ---------------- zeroing ------------------------------------------------
__global__ void zero_csum() {
    int i = blockIdx.x * blockDim.x + threadIdx.x;
    const int n1 = N_EVT * D / 4;
    const int n2 = N_EVT / 4;
    float4 z = make_float4(0.f, 0.f, 0.f, 0.f);
    if (i < n1) reinterpret_cast<float4*>(g_csum)[i] = z;
    if (i < n2) reinterpret_cast<float4*>(g_cnt)[i]  = z;
}

__global__ void zero_teff() {
    int i = blockIdx.x * blockDim.x + threadIdx.x;
    if (i < N_OBJ * D / 4)
        reinterpret_cast<float4*>(g_teff)[i] = make_float4(0.f, 0.f, 0.f, 0.f);
}

// =====================================================================
// tf32 mma.sync GEMM: cp.async 3-stage pipeline, BK=32, ldmatrix loads,
// SW128-style XOR swizzle on dense 128B SMEM rows. (R10 structure.)
// CTA tile 128x128, 256 threads = 8 warps (4m x 2n), warp 32x64.
// W row stride = K. CTX=1: A = [evX | csum*inv(cnt)] (row stride 128 each),
// K=256; epilogue adds beta*cvec. g_cnt/g_cvec read directly.
// =====================================================================
#define BK     32
#define STAGES 3
#define STG_W  (128 * 32)
#define GEMM_SMEM (STAGES * STG_W * 2 * 4)    // 98304 bytes

template<int RELU, int CTX, int ACVT, int RNDOUT>
__global__ __launch_bounds__(256, 2)
void gemm_mma(const float* __restrict__ A, const float* __restrict__ A2,
              const float* __restrict__ W,
              const float* __restrict__ bias, float* __restrict__ C,
              int M, int N, int K) {
    extern __shared__ uint32_t sm[];
    uint32_t* As = sm;
    uint32_t* Bs = sm + STAGES * STG_W;
    __shared__ float sinv[128];
    __shared__ float sbeta[128];

    const int tid = threadIdx.x;
    const int wid = tid >> 5;
    const int lane = tid & 31;
    const int gq = lane >> 2;
    const int tg = lane & 3;
    const int warp_m = wid >> 1;
    const int warp_n = wid & 1;
    const int bm = blockIdx.y * 128;
    const int bn = blockIdx.x * 128;

    const uint32_t aAs = smem_u32(As);
    const uint32_t aBs = smem_u32(Bs);

    const int r0 = tid >> 3;
    const int cb = (tid & 7) * 16;
    const int c4f = (tid & 7) * 4;

    uint32_t rowbA[2], swzA[2];
    #pragma unroll
    for (int mt = 0; mt < 2; mt++) {
        int row = warp_m * 32 + mt * 16 + (lane & 15);
        rowbA[mt] = (uint32_t)row * 128;
        swzA[mt] = (uint32_t)(row & 7) << 4;
    }
    const uint32_t hiA = (uint32_t)(lane >> 4) << 4;
    uint32_t rowbB[4], swzB[4];
    #pragma unroll
    for (int j = 0; j < 4; j++) {
        int n = warp_n * 64 + j * 16 + (lane & 7) + (((lane >> 4) & 1) << 3);
        rowbB[j] = (uint32_t)n * 128;
        swzB[j] = (uint32_t)(n & 7) << 4;
    }
    const uint32_t hiB = (lane & 8) ? 16u : 0u;

    float acc[2][8][4];
    #pragma unroll
    for (int i = 0; i < 2; i++)
        #pragma unroll
        for (int j = 0; j < 8; j++)
            #pragma unroll
            for (int q = 0; q < 4; q++) acc[i][j][q] = 0.f;

    const int CHUNKS = K >> 5;

    auto issue = [&](int c) {
        if (c < CHUNKS) {
            const int p = (c % STAGES);
            const int k0 = c * BK + c4f;
            const uint32_t dsw = (uint32_t)cb ^ ((uint32_t)(r0 & 7) << 4);
            #pragma unroll
            for (int h = 0; h < 4; h++) {
                int r = r0 + h * 32;
                const float* srcA;
                if (CTX) {
                    srcA = (k0 < 128)
                         ? &A [(size_t)(bm + r) * 128 + k0]
                         : &A2[(size_t)(bm + r) * 128 + (k0 - 128)];
                } else {
                    srcA = &A[(size_t)(bm + r) * K + k0];
                }
                int szA = (bm + r < M) ? 16 : 0;
                uint32_t doff = (uint32_t)(p * STG_W * 4) + (uint32_t)r * 128 + dsw;
                cpasync16(aAs + doff, srcA, szA);
                cpasync16(aBs + doff, &W[(size_t)(bn + r) * K + k0], 16);
            }
        }
        asm volatile("cp.async.commit_group;");
    };

    float invr[2][2];
    if (CTX) {
        if (tid < 128) {
            int r = bm + tid;
            float cv = (r < M) ? __ldg(&g_cnt[r]) : 1.0f;
            float iv = 1.0f / fmaxf(cv, 1.0f);
            sinv[tid] = iv;
            sbeta[tid] = cv * iv;
        }
    }

    issue(0); issue(1);
    if (CTX) __syncthreads();

    if (CTX) {
        #pragma unroll
        for (int mt = 0; mt < 2; mt++) {
            int row = warp_m * 32 + mt * 16 + gq;
            invr[mt][0] = sinv[row];
            invr[mt][1] = sinv[row + 8];
        }
    }

    for (int c = 0; c < CHUNKS; c++) {
        const int p = (c % STAGES);
        asm volatile("cp.async.wait_group 1;");
        __syncthreads();
        issue(c + 2);

        const bool scale = CTX && (c >= 4);
        const uint32_t stA = aAs + (uint32_t)(p * STG_W) * 4;
        const uint32_t stB = aBs + (uint32_t)(p * STG_W) * 4;
        #pragma unroll
        for (int ks = 0; ks < 4; ks++) {
            const uint32_t kc = (uint32_t)ks * 32;
            uint32_t af[2][4], bf[4][4];
            #pragma unroll
            for (int mt = 0; mt < 2; mt++)
                ldmx4(af[mt], stA + rowbA[mt] + ((kc + hiA) ^ swzA[mt]));
            #pragma unroll
            for (int j = 0; j < 4; j++)
                ldmx4(bf[j], stB + rowbB[j] + ((kc + hiB) ^ swzB[j]));

            if (ACVT) {
                #pragma unroll
                for (int mt = 0; mt < 2; mt++) {
                    float f0 = __uint_as_float(af[mt][0]);
                    float f1 = __uint_as_float(af[mt][1]);
                    float f2 = __uint_as_float(af[mt][2]);
                    float f3 = __uint_as_float(af[mt][3]);
                    if (scale) {
                        f0 *= invr[mt][0]; f1 *= invr[mt][1];
                        f2 *= invr[mt][0]; f3 *= invr[mt][1];
                    }
                    af[mt][0] = tf32r(f0); af[mt][1] = tf32r(f1);
                    af[mt][2] = tf32r(f2); af[mt][3] = tf32r(f3);
                }
            }
            #pragma unroll
            for (int mt = 0; mt < 2; mt++)
                #pragma unroll
                for (int nt = 0; nt < 8; nt++)
                    mma_tf32(acc[mt][nt], af[mt], &bf[nt >> 1][(nt & 1) * 2]);
        }
    }

    // epilogue
    #pragma unroll
    for (int mt = 0; mt < 2; mt++) {
        #pragma unroll
        for (int half = 0; half < 2; half++) {
            int mrow = warp_m * 32 + mt * 16 + gq + half * 8;
            int m = bm + mrow;
            if (m >= M) continue;
            float beta = CTX ? sbeta[mrow] : 0.f;
            #pragma unroll
            for (int nt = 0; nt < 8; nt++) {
                int n = bn + warp_n * 64 + nt * 8 + tg * 2;
                float2 bb = *reinterpret_cast<const float2*>(&bias[n]);
                float2 o;
                o.x = acc[mt][nt][half * 2 + 0] + bb.x;
                o.y = acc[mt][nt][half * 2 + 1] + bb.y;
                if (CTX) {
                    float2 cv = *reinterpret_cast<const float2*>(&g_cvec[n]);
                    o.x = fmaf(beta, cv.x, o.x);
                    o.y = fmaf(beta, cv.y, o.y);
                }
                if (RELU) { o.x = fmaxf(o.x, 0.f); o.y = fmaxf(o.y, 0.f); }
                if (RNDOUT) {
                    o.x = __uint_as_float(tf32r(o.x));
                    o.y = __uint_as_float(tf32r(o.y));
                }
                *reinterpret_cast<float2*>(&C[(size_t)m * N + n]) = o;
            }
        }
    }
}

// ---------------- edge scatter: objX[o] -> sum into events + counts -----
__global__ void scatter_obj_to_evt(const int* __restrict__ obj_idx,
                                   const int* __restrict__ evt_idx,
                                   const float* __restrict__ objX) {
    int gid = blockIdx.x * blockDim.x + threadIdx.x;
    if (gid >= N_EDGE * 32) return;
    int e = gid >> 5;
    int c = gid & 31;
    int o  = __ldg(obj_idx + e);
    int ev = __ldg(evt_idx + e);
    float4 v = *reinterpret_cast<const float4*>(&objX[(size_t)o * D + c * 4]);
    red4(&g_csum[(size_t)ev * D + c * 4], v);
    if (c == 0) atomicAdd(&g_cnt[ev], 1.0f);
}

// ---------------- edge scatter: h_impulse[evt] -> sum into objects ------
__global__ void scatter_evt_to_obj(const int* __restrict__ obj_idx,
                                   const int* __restrict__ evt_idx,
                                   const float* __restrict__ himp) {
    int gid = blockIdx.x * blockDim.x + threadIdx.x;
    if (gid >= N_EDGE * 32) return;
    int e = gid >> 5;
    int c = gid & 31;
    int o  = __ldg(obj_idx + e);
    int ev = __ldg(evt_idx + e);
    float4 v = *reinterpret_cast<const float4*>(&himp[(size_t)ev * D + c * 4]);
    red4(&g_teff[(size_t)o * D + c * 4], v);
}

// ---------------- GRU gate math -----------------------------------------
__global__ void gru_gates(const float* __restrict__ objX, float* __restrict__ out) {
    int gid = blockIdx.x * blockDim.x + threadIdx.x;
    if (gid >= N_OBJ * D) return;
    int r = gid >> 7;
    int d = gid & 127;
    size_t base = (size_t)r * 3 * D + d;
    float ir = g_gi[base], iz = g_gi[base + D], in_ = g_gi[base + 2 * D];
    float hr = g_gh[base], hz = g_gh[base + D], hn  = g_gh[base + 2 * D];
    float h = objX[(size_t)r * D + d];
    float rg = sigmoidf_(ir + hr);
    float z  = sigmoidf_(iz + hz);
    float n  = tanhf(in_ + rg * hn);
    out[(size_t)r * D + d] = (1.0f - z) * n + z * h;
}

// ---------------- launch ------------------------------------------------
extern "C" void kernel_launch(void* const* d_in, const int* in_sizes, int n_in,
                              void* d_out, int out_size) {
    const float* event_X  = (const float*)d_in[0];
    const float* object_X = (const float*)d_in[1];
    const int*   evt_idx  = (const int*)d_in[2];
    const int*   obj_idx  = (const int*)d_in[3];
    const float* Wa  = (const float*)d_in[4];
    const float* ba  = (const float*)d_in[5];
    const float* W1  = (const float*)d_in[6];
    const float* b1  = (const float*)d_in[7];
    const float* W2  = (const float*)d_in[8];
    const float* b2  = (const float*)d_in[9];
    const float* Wih = (const float*)d_in[10];
    const float* Whh = (const float*)d_in[11];
    const float* bih = (const float*)d_in[12];
    const float* bhh = (const float*)d_in[13];

    float* out = (float*)d_out;
    float* out_newobj = out;                       // [N_OBJ, 128]
    float* out_himp   = out + (size_t)N_OBJ * D;   // [N_EVT, 128]

    float* csum  = nullptr; cudaGetSymbolAddress((void**)&csum,  g_csum);
    float* h1    = nullptr; cudaGetSymbolAddress((void**)&h1,    g_h1);
    float* teff  = nullptr; cudaGetSymbolAddress((void**)&teff,  g_teff);
    float* gi    = nullptr; cudaGetSymbolAddress((void**)&gi,    g_gi);
    float* gh    = nullptr; cudaGetSymbolAddress((void**)&gh,    g_gh);
    float* wr    = nullptr; cudaGetSymbolAddress((void**)&wr,    g_wrnd);

    static cudaStream_t sW = nullptr;
    static cudaEvent_t eFork, eW, eGh, eZT;
    if (!sW) {
        cudaStreamCreateWithFlags(&sW, cudaStreamNonBlocking);
        cudaEventCreateWithFlags(&eFork, cudaEventDisableTiming);
        cudaEventCreateWithFlags(&eW,   cudaEventDisableTiming);
        cudaEventCreateWithFlags(&eGh,  cudaEventDisableTiming);
        cudaEventCreateWithFlags(&eZT,  cudaEventDisableTiming);
        cudaFuncSetAttribute(gemm_mma<0, 0, 1, 0>,
            cudaFuncAttributeMaxDynamicSharedMemorySize, GEMM_SMEM);
        cudaFuncSetAttribute(gemm_mma<1, 1, 1, 1>,
            cudaFuncAttributeMaxDynamicSharedMemorySize, GEMM_SMEM);
        cudaFuncSetAttribute(gemm_mma<0, 0, 0, 0>,
            cudaFuncAttributeMaxDynamicSharedMemorySize, GEMM_SMEM);
    }

    // fork side stream: weight prep, gh GEMM, teff zero
    cudaEventRecord(eFork, 0);
    cudaStreamWaitEvent(sW, eFork, 0);
    round_weights<<<(163840 + 255) / 256, 256, 0, sW>>>(W1, W2, Wih, Whh);
    wc_kernel<<<128, 128, 0, sW>>>(W1, Wa, ba);
    cudaEventRecord(eW, sW);
    gemm_mma<0, 0, 1, 0><<<dim3(3, (N_OBJ + 127) / 128), 256, GEMM_SMEM, sW>>>(
        object_X, nullptr, wr + WR_WHH, bhh, gh, N_OBJ, 3 * D, D);
    cudaEventRecord(eGh, sW);
    zero_teff<<<(N_OBJ * D / 4 + 255) / 256, 256, 0, sW>>>();
    cudaEventRecord(eZT, sW);

    // main: zero csum+cnt -> scatter objX into events
    zero_csum<<<(N_EVT * D / 4 + 255) / 256, 256>>>();
    scatter_obj_to_evt<<<(N_EDGE * 32 + 255) / 256, 256>>>(obj_idx, evt_idx,
                                                           object_X);

    // h1 = relu(evX@W1a^T + mean_obj@Wc^T + b1 + beta*cvec)
    cudaStreamWaitEvent(0, eW, 0);
    gemm_mma<1, 1, 1, 1><<<dim3(1, (N_EVT + 127) / 128), 256, GEMM_SMEM>>>(
        event_X, csum, wr + WR_W1, b1, h1, N_EVT, D, 2 * D);

    // h_impulse = h1 @ W2^T + b2 -> output
    gemm_mma<0, 0, 0, 0><<<dim3(1, (N_EVT + 127) / 128), 256, GEMM_SMEM>>>(
        h1, nullptr, wr + WR_W2, b2, out_himp, N_EVT, D, D);

    // scatter-add impulses into objects (teff zeroed on side stream)
    cudaStreamWaitEvent(0, eZT, 0);
    scatter_evt_to_obj<<<(N_EDGE * 32 + 255) / 256, 256>>>(obj_idx, evt_idx,
                                                           out_himp);

    // gi = total_effect @ Wih^T + bih
    gemm_mma<0, 0, 1, 0><<<dim3(3, (N_OBJ + 127) / 128), 256, GEMM_SMEM>>>(
        teff, nullptr, wr + WR_WIH, bih, gi, N_OBJ, 3 * D, D);

    // join gh, then GRU gates -> new_object_X
    cudaStreamWaitEvent(0, eGh, 0);
    gru_gates<<<(N_OBJ * D + 255) / 256, 256>>>(object_X, out_newobj);
}

// round 17
// speedup vs baseline: 1.4901x; 1.1093x over previous
#include <cuda_runtime.h>
#include <math.h>
#include <stdint.h>

#define N_OBJ  100000
#define N_EVT  200000
#define N_EDGE 1000000
#define D      128

// ---------------- scratch (device globals; no allocation) ----------------
__device__ float g_csum [(size_t)N_EVT * D];      // scatter-sum of objX rows
__device__ float g_cnt  [N_EVT];                  // edge counts per event
__device__ float g_h1   [(size_t)N_EVT * D];      // relu(...), tf32-rounded
__device__ float g_teff [(size_t)N_OBJ * D];      // scatter-add into objects
__device__ float g_gi   [(size_t)N_OBJ * 3 * D];  // x @ Wih^T + bih
__device__ float g_gh   [(size_t)N_OBJ * 3 * D];  // h @ Whh^T + bhh
__device__ float g_wrnd [163840];                 // tf32-rounded weights
__device__ float g_cvec [128];                    // W1b @ ba (fp32)

#define WR_WA   0        // unused slot (layout stability)
#define WR_W1   16384    // fused [W1a | Wc] rows of 256
#define WR_W2   49152
#define WR_WIH  65536
#define WR_WHH  114688

// ---------------- helpers ----------------
__device__ __forceinline__ uint32_t smem_u32(const void* p) {
    uint32_t a;
    asm("{ .reg .u64 t; cvta.to.shared.u64 t, %1; cvt.u32.u64 %0, t; }"
        : "=r"(a) : "l"(p));
    return a;
}

__device__ __forceinline__ uint32_t tf32r(float f) {
    uint32_t o;
    asm("cvt.rna.tf32.f32 %0, %1;" : "=r"(o) : "f"(f));
    return o;
}

__device__ __forceinline__ void cpasync16(uint32_t dst, const void* src, int sz) {
    asm volatile("cp.async.cg.shared.global [%0], [%1], 16, %2;"
                 :: "r"(dst), "l"(src), "r"(sz));
}

__device__ __forceinline__ void ldmx4(uint32_t* r, uint32_t addr) {
    asm volatile(
        "ldmatrix.sync.aligned.x4.m8n8.shared.b16 {%0,%1,%2,%3}, [%4];"
        : "=r"(r[0]), "=r"(r[1]), "=r"(r[2]), "=r"(r[3]) : "r"(addr));
}

__device__ __forceinline__ void red4(float* addr, float4 v) {
    asm volatile("red.global.add.v4.f32 [%0], {%1, %2, %3, %4};"
                 :: "l"(addr), "f"(v.x), "f"(v.y), "f"(v.z), "f"(v.w)
                 : "memory");
}

__device__ __forceinline__ float sigmoidf_(float x) {
    return 1.0f / (1.0f + expf(-x));
}

__device__ __forceinline__ void mma_tf32(float* c, const uint32_t* a,
                                         const uint32_t* b) {
    asm volatile(
        "mma.sync.aligned.m16n8k8.row.col.f32.tf32.tf32.f32 "
        "{%0,%1,%2,%3}, {%4,%5,%6,%7}, {%8,%9}, {%0,%1,%2,%3};"
        : "+f"(c[0]), "+f"(c[1]), "+f"(c[2]), "+f"(c[3])
        : "r"(a[0]), "r"(a[1]), "r"(a[2]), "r"(a[3]), "r"(b[0]), "r"(b[1]));
}

// ---------------- weight pre-rounding (skips W1 right half) -------------
__global__ void round_weights(const float* __restrict__ W1,
                              const float* __restrict__ W2,
                              const float* __restrict__ Wih,
                              const float* __restrict__ Whh) {
    int i = blockIdx.x * blockDim.x + threadIdx.x;
    if (i < WR_W1 || i >= 163840) return;
    float v;
    if (i < WR_W2) {
        int local = i - WR_W1;
        if ((local & 255) >= 128) return;   // Wc half, filled by wc_kernel
        v = W1[local];
    }
    else if (i < WR_WIH) v = W2 [i - WR_W2];
    else if (i < WR_WHH) v = Wih[i - WR_WIH];
    else                 v = Whh[i - WR_WHH];
    g_wrnd[i] = __uint_as_float(tf32r(v));
}

// ---------------- Wc = W1b @ Wa  (and cvec = W1b @ ba) ------------------
__global__ void wc_kernel(const float* __restrict__ W1,
                          const float* __restrict__ Wa,
                          const float* __restrict__ ba) {
    __shared__ float w1b[128];
    const int n = blockIdx.x;
    const int j = threadIdx.x;
    w1b[j] = W1[n * 256 + 128 + j];
    __syncthreads();
    float s = 0.f;
    #pragma unroll 4
    for (int k = 0; k < 128; k++)
        s = fmaf(w1b[k], Wa[k * 128 + j], s);
    g_wrnd[WR_W1 + n * 256 + 128 + j] = __uint_as_float(tf32r(s));
    if (j == 0) {
        float cs = 0.f;
        for (int k = 0; k < 128; k++) cs = fmaf(w1b[k], ba[k], cs);
        g_cvec[n] = cs;
    }
}

// ---------------- zeroing ------------------------------------------------
__global__ void zero_csum() {
    int i = blockIdx.x * blockDim.x + threadIdx.x;
    const int n1 = N_EVT * D / 4;
    const int n2 = N_EVT / 4;
    float4 z = make_float4(0.f, 0.f, 0.f, 0.f);
    if (i < n1) reinterpret_cast<float4*>(g_csum)[i] = z;
    if (i < n2) reinterpret_cast<float4*>(g_cnt)[i]  = z;
}

__global__ void zero_teff() {
    int i = blockIdx.x * blockDim.x + threadIdx.x;
    if (i < N_OBJ * D / 4)
        reinterpret_cast<float4*>(g_teff)[i] = make_float4(0.f, 0.f, 0.f, 0.f);
}

// =====================================================================
// tf32 mma.sync GEMM: cp.async 3-stage pipeline, BK=32, ldmatrix loads,
// SW128-style XOR swizzle on dense 128B SMEM rows. (R10 structure.)
// CTA tile 128x128, 256 threads = 8 warps (4m x 2n), warp 32x64.
// W row stride = K. CTX=1: A = [evX | csum*inv(cnt)] (row stride 128 each),
// K=256; epilogue adds beta*cvec. g_cnt/g_cvec read directly.
// =====================================================================
#define BK     32
#define STAGES 3
#define STG_W  (128 * 32)
#define GEMM_SMEM (STAGES * STG_W * 2 * 4)    // 98304 bytes

template<int RELU, int CTX, int ACVT, int RNDOUT>
__global__ __launch_bounds__(256, 2)
void gemm_mma(const float* __restrict__ A, const float* __restrict__ A2,
              const float* __restrict__ W,
              const float* __restrict__ bias, float* __restrict__ C,
              int M, int N, int K) {
    extern __shared__ uint32_t sm[];
    uint32_t* As = sm;
    uint32_t* Bs = sm + STAGES * STG_W;
    __shared__ float sinv[128];
    __shared__ float sbeta[128];

    const int tid = threadIdx.x;
    const int wid = tid >> 5;
    const int lane = tid & 31;
    const int gq = lane >> 2;
    const int tg = lane & 3;
    const int warp_m = wid >> 1;
    const int warp_n = wid & 1;
    const int bm = blockIdx.y * 128;
    const int bn = blockIdx.x * 128;

    const uint32_t aAs = smem_u32(As);
    const uint32_t aBs = smem_u32(Bs);

    const int r0 = tid >> 3;
    const int cb = (tid & 7) * 16;
    const int c4f = (tid & 7) * 4;

    uint32_t rowbA[2], swzA[2];
    #pragma unroll
    for (int mt = 0; mt < 2; mt++) {
        int row = warp_m * 32 + mt * 16 + (lane & 15);
        rowbA[mt] = (uint32_t)row * 128;
        swzA[mt] = (uint32_t)(row & 7) << 4;
    }
    const uint32_t hiA = (uint32_t)(lane >> 4) << 4;
    uint32_t rowbB[4], swzB[4];
    #pragma unroll
    for (int j = 0; j < 4; j++) {
        int n = warp_n * 64 + j * 16 + (lane & 7) + (((lane >> 4) & 1) << 3);
        rowbB[j] = (uint32_t)n * 128;
        swzB[j] = (uint32_t)(n & 7) << 4;
    }
    const uint32_t hiB = (lane & 8) ? 16u : 0u;

    float acc[2][8][4];
    #pragma unroll
    for (int i = 0; i < 2; i++)
        #pragma unroll
        for (int j = 0; j < 8; j++)
            #pragma unroll
            for (int q = 0; q < 4; q++) acc[i][j][q] = 0.f;

    const int CHUNKS = K >> 5;

    auto issue = [&](int c) {
        if (c < CHUNKS) {
            const int p = (c % STAGES);
            const int k0 = c * BK + c4f;
            const uint32_t dsw = (uint32_t)cb ^ ((uint32_t)(r0 & 7) << 4);
            #pragma unroll
            for (int h = 0; h < 4; h++) {
                int r = r0 + h * 32;
                const float* srcA;
                if (CTX) {
                    srcA = (k0 < 128)
                         ? &A [(size_t)(bm + r) * 128 + k0]
                         : &A2[(size_t)(bm + r) * 128 + (k0 - 128)];
                } else {
                    srcA = &A[(size_t)(bm + r) * K + k0];
                }
                int szA = (bm + r < M) ? 16 : 0;
                uint32_t doff = (uint32_t)(p * STG_W * 4) + (uint32_t)r * 128 + dsw;
                cpasync16(aAs + doff, srcA, szA);
                cpasync16(aBs + doff, &W[(size_t)(bn + r) * K + k0], 16);
            }
        }
        asm volatile("cp.async.commit_group;");
    };

    float invr[2][2];
    if (CTX) {
        if (tid < 128) {
            int r = bm + tid;
            float cv = (r < M) ? __ldg(&g_cnt[r]) : 1.0f;
            float iv = 1.0f / fmaxf(cv, 1.0f);
            sinv[tid] = iv;
            sbeta[tid] = cv * iv;
        }
    }

    issue(0); issue(1);
    if (CTX) __syncthreads();

    if (CTX) {
        #pragma unroll
        for (int mt = 0; mt < 2; mt++) {
            int row = warp_m * 32 + mt * 16 + gq;
            invr[mt][0] = sinv[row];
            invr[mt][1] = sinv[row + 8];
        }
    }

    for (int c = 0; c < CHUNKS; c++) {
        const int p = (c % STAGES);
        asm volatile("cp.async.wait_group 1;");
        __syncthreads();
        issue(c + 2);

        const bool scale = CTX && (c >= 4);
        const uint32_t stA = aAs + (uint32_t)(p * STG_W) * 4;
        const uint32_t stB = aBs + (uint32_t)(p * STG_W) * 4;
        #pragma unroll
        for (int ks = 0; ks < 4; ks++) {
            const uint32_t kc = (uint32_t)ks * 32;
            uint32_t af[2][4], bf[4][4];
            #pragma unroll
            for (int mt = 0; mt < 2; mt++)
                ldmx4(af[mt], stA + rowbA[mt] + ((kc + hiA) ^ swzA[mt]));
            #pragma unroll
            for (int j = 0; j < 4; j++)
                ldmx4(bf[j], stB + rowbB[j] + ((kc + hiB) ^ swzB[j]));

            if (ACVT) {
                #pragma unroll
                for (int mt = 0; mt < 2; mt++) {
                    float f0 = __uint_as_float(af[mt][0]);
                    float f1 = __uint_as_float(af[mt][1]);
                    float f2 = __uint_as_float(af[mt][2]);
                    float f3 = __uint_as_float(af[mt][3]);
                    if (scale) {
                        f0 *= invr[mt][0]; f1 *= invr[mt][1];
                        f2 *= invr[mt][0]; f3 *= invr[mt][1];
                    }
                    af[mt][0] = tf32r(f0); af[mt][1] = tf32r(f1);
                    af[mt][2] = tf32r(f2); af[mt][3] = tf32r(f3);
                }
            }
            #pragma unroll
            for (int mt = 0; mt < 2; mt++)
                #pragma unroll
                for (int nt = 0; nt < 8; nt++)
                    mma_tf32(acc[mt][nt], af[mt], &bf[nt >> 1][(nt & 1) * 2]);
        }
    }

    // epilogue
    #pragma unroll
    for (int mt = 0; mt < 2; mt++) {
        #pragma unroll
        for (int half = 0; half < 2; half++) {
            int mrow = warp_m * 32 + mt * 16 + gq + half * 8;
            int m = bm + mrow;
            if (m >= M) continue;
            float beta = CTX ? sbeta[mrow] : 0.f;
            #pragma unroll
            for (int nt = 0; nt < 8; nt++) {
                int n = bn + warp_n * 64 + nt * 8 + tg * 2;
                float2 bb = *reinterpret_cast<const float2*>(&bias[n]);
                float2 o;
                o.x = acc[mt][nt][half * 2 + 0] + bb.x;
                o.y = acc[mt][nt][half * 2 + 1] + bb.y;
                if (CTX) {
                    float2 cv = *reinterpret_cast<const float2*>(&g_cvec[n]);
                    o.x = fmaf(beta, cv.x, o.x);
                    o.y = fmaf(beta, cv.y, o.y);
                }
                if (RELU) { o.x = fmaxf(o.x, 0.f); o.y = fmaxf(o.y, 0.f); }
                if (RNDOUT) {
                    o.x = __uint_as_float(tf32r(o.x));
                    o.y = __uint_as_float(tf32r(o.y));
                }
                *reinterpret_cast<float2*>(&C[(size_t)m * N + n]) = o;
            }
        }
    }
}

// -------- edge scatter: objX[o] -> sum into events (2 float4s/thread) ---
__global__ void scatter_obj_to_evt(const int* __restrict__ obj_idx,
                                   const int* __restrict__ evt_idx,
                                   const float* __restrict__ objX) {
    int gid = blockIdx.x * blockDim.x + threadIdx.x;
    if (gid >= N_EDGE * 16) return;
    int e = gid >> 4;
    int c = gid & 15;
    int o  = __ldg(obj_idx + e);
    int ev = __ldg(evt_idx + e);
    const float4* src = reinterpret_cast<const float4*>(&objX[(size_t)o * D]);
    float4* dst = reinterpret_cast<float4*>(&g_csum[(size_t)ev * D]);
    float4 v0 = src[c];
    float4 v1 = src[c + 16];
    red4(reinterpret_cast<float*>(dst + c), v0);
    red4(reinterpret_cast<float*>(dst + c + 16), v1);
    if (c == 0) atomicAdd(&g_cnt[ev], 1.0f);
}

// -------- edge scatter: himp[ev] -> sum into objects (2 float4s/thread) --
__global__ void scatter_evt_to_obj(const int* __restrict__ obj_idx,
                                   const int* __restrict__ evt_idx,
                                   const float* __restrict__ himp) {
    int gid = blockIdx.x * blockDim.x + threadIdx.x;
    if (gid >= N_EDGE * 16) return;
    int e = gid >> 4;
    int c = gid & 15;
    int o  = __ldg(obj_idx + e);
    int ev = __ldg(evt_idx + e);
    const float4* src = reinterpret_cast<const float4*>(&himp[(size_t)ev * D]);
    float4* dst = reinterpret_cast<float4*>(&g_teff[(size_t)o * D]);
    float4 v0 = src[c];
    float4 v1 = src[c + 16];
    red4(reinterpret_cast<float*>(dst + c), v0);
    red4(reinterpret_cast<float*>(dst + c + 16), v1);
}

// ---------------- GRU gate math (float4 vectorized) ----------------------
__global__ void gru_gates(const float* __restrict__ objX, float* __restrict__ out) {
    int gid = blockIdx.x * blockDim.x + threadIdx.x;
    if (gid >= N_OBJ * 32) return;
    int r = gid >> 5;
    int q = gid & 31;           // float4 index within row
    size_t base = (size_t)r * 96 + q;   // row stride 384 floats = 96 float4s
    const float4* gi4 = reinterpret_cast<const float4*>(g_gi);
    const float4* gh4 = reinterpret_cast<const float4*>(g_gh);
    float4 ir = gi4[base], iz = gi4[base + 32], in_ = gi4[base + 64];
    float4 hr = gh4[base], hz = gh4[base + 32], hn  = gh4[base + 64];
    float4 h = reinterpret_cast<const float4*>(objX)[(size_t)r * 32 + q];
    float4 o;
    {
        float rg = sigmoidf_(ir.x + hr.x);
        float z  = sigmoidf_(iz.x + hz.x);
        float n  = tanhf(in_.x + rg * hn.x);
        o.x = (1.0f - z) * n + z * h.x;
    }
    {
        float rg = sigmoidf_(ir.y + hr.y);
        float z  = sigmoidf_(iz.y + hz.y);
        float n  = tanhf(in_.y + rg * hn.y);
        o.y = (1.0f - z) * n + z * h.y;
    }
    {
        float rg = sigmoidf_(ir.z + hr.z);
        float z  = sigmoidf_(iz.z + hz.z);
        float n  = tanhf(in_.z + rg * hn.z);
        o.z = (1.0f - z) * n + z * h.z;
    }
    {
        float rg = sigmoidf_(ir.w + hr.w);
        float z  = sigmoidf_(iz.w + hz.w);
        float n  = tanhf(in_.w + rg * hn.w);
        o.w = (1.0f - z) * n + z * h.w;
    }
    reinterpret_cast<float4*>(out)[(size_t)r * 32 + q] = o;
}

// ---------------- launch ------------------------------------------------
extern "C" void kernel_launch(void* const* d_in, const int* in_sizes, int n_in,
                              void* d_out, int out_size) {
    const float* event_X  = (const float*)d_in[0];
    const float* object_X = (const float*)d_in[1];
    const int*   evt_idx  = (const int*)d_in[2];
    const int*   obj_idx  = (const int*)d_in[3];
    const float* Wa  = (const float*)d_in[4];
    const float* ba  = (const float*)d_in[5];
    const float* W1  = (const float*)d_in[6];
    const float* b1  = (const float*)d_in[7];
    const float* W2  = (const float*)d_in[8];
    const float* b2  = (const float*)d_in[9];
    const float* Wih = (const float*)d_in[10];
    const float* Whh = (const float*)d_in[11];
    const float* bih = (const float*)d_in[12];
    const float* bhh = (const float*)d_in[13];

    float* out = (float*)d_out;
    float* out_newobj = out;                       // [N_OBJ, 128]
    float* out_himp   = out + (size_t)N_OBJ * D;   // [N_EVT, 128]

    float* csum  = nullptr; cudaGetSymbolAddress((void**)&csum,  g_csum);
    float* h1    = nullptr; cudaGetSymbolAddress((void**)&h1,    g_h1);
    float* teff  = nullptr; cudaGetSymbolAddress((void**)&teff,  g_teff);
    float* gi    = nullptr; cudaGetSymbolAddress((void**)&gi,    g_gi);
    float* gh    = nullptr; cudaGetSymbolAddress((void**)&gh,    g_gh);
    float* wr    = nullptr; cudaGetSymbolAddress((void**)&wr,    g_wrnd);

    static cudaStream_t sW = nullptr;
    static cudaEvent_t eFork, eW, eGh, eZT;
    if (!sW) {
        cudaStreamCreateWithFlags(&sW, cudaStreamNonBlocking);
        cudaEventCreateWithFlags(&eFork, cudaEventDisableTiming);
        cudaEventCreateWithFlags(&eW,   cudaEventDisableTiming);
        cudaEventCreateWithFlags(&eGh,  cudaEventDisableTiming);
        cudaEventCreateWithFlags(&eZT,  cudaEventDisableTiming);
        cudaFuncSetAttribute(gemm_mma<0, 0, 1, 0>,
            cudaFuncAttributeMaxDynamicSharedMemorySize, GEMM_SMEM);
        cudaFuncSetAttribute(gemm_mma<1, 1, 1, 1>,
            cudaFuncAttributeMaxDynamicSharedMemorySize, GEMM_SMEM);
        cudaFuncSetAttribute(gemm_mma<0, 0, 0, 0>,
            cudaFuncAttributeMaxDynamicSharedMemorySize, GEMM_SMEM);
    }

    // fork side stream: weight prep, gh GEMM, teff zero
    cudaEventRecord(eFork, 0);
    cudaStreamWaitEvent(sW, eFork, 0);
    round_weights<<<(163840 + 255) / 256, 256, 0, sW>>>(W1, W2, Wih, Whh);
    wc_kernel<<<128, 128, 0, sW>>>(W1, Wa, ba);
    cudaEventRecord(eW, sW);
    gemm_mma<0, 0, 1, 0><<<dim3(3, (N_OBJ + 127) / 128), 256, GEMM_SMEM, sW>>>(
        object_X, nullptr, wr + WR_WHH, bhh, gh, N_OBJ, 3 * D, D);
    cudaEventRecord(eGh, sW);
    zero_teff<<<(N_OBJ * D / 4 + 255) / 256, 256, 0, sW>>>();
    cudaEventRecord(eZT, sW);

    // main: zero csum+cnt -> scatter objX into events
    zero_csum<<<(N_EVT * D / 4 + 255) / 256, 256>>>();
    scatter_obj_to_evt<<<(N_EDGE * 16 + 255) / 256, 256>>>(obj_idx, evt_idx,
                                                           object_X);

    // h1 = relu(evX@W1a^T + mean_obj@Wc^T + b1 + beta*cvec)
    cudaStreamWaitEvent(0, eW, 0);
    gemm_mma<1, 1, 1, 1><<<dim3(1, (N_EVT + 127) / 128), 256, GEMM_SMEM>>>(
        event_X, csum, wr + WR_W1, b1, h1, N_EVT, D, 2 * D);

    // h_impulse = h1 @ W2^T + b2 -> output
    gemm_mma<0, 0, 0, 0><<<dim3(1, (N_EVT + 127) / 128), 256, GEMM_SMEM>>>(
        h1, nullptr, wr + WR_W2, b2, out_himp, N_EVT, D, D);

    // scatter-add impulses into objects (teff zeroed on side stream)
    cudaStreamWaitEvent(0, eZT, 0);
    scatter_evt_to_obj<<<(N_EDGE * 16 + 255) / 256, 256>>>(obj_idx, evt_idx,
                                                           out_himp);

    // gi = total_effect @ Wih^T + bih
    gemm_mma<0, 0, 1, 0><<<dim3(3, (N_OBJ + 127) / 128), 256, GEMM_SMEM>>>(
        teff, nullptr, wr + WR_WIH, bih, gi, N_OBJ, 3 * D, D);

    // join gh, then GRU gates -> new_object_X
    cudaStreamWaitEvent(0, eGh, 0);
    gru_gates<<<(N_OBJ * 32 + 255) / 256, 256>>>(object_X, out_newobj);
}